// round 8
// baseline (speedup 1.0000x reference)
#include <cuda_runtime.h>
#include <math.h>
#include <stdint.h>

#define NN 50000
#define EE 800000
#define DD 128
#define OUTC 64
#define NBLK ((NN + 1023) / 1024)   // 49 scan blocks

typedef unsigned long long u64;

// ---------------- scratch (device globals; no allocation allowed) ----------
__device__ int   g_ei_is64;
__device__ int   g_m_is32;
__device__ unsigned char g_M[NN * DD];
__device__ int   g_deg[NN];
__device__ float g_dinv[NN];
__device__ int   g_off[NN + 1];
__device__ int   g_cur[NN];
__device__ int   g_bsum[64];
__device__ int   g_src[EE];
__device__ float g_xtA[NN * DD];    // x_tilde ping buffer (pre-scaled by dinv[row])
__device__ float g_xtB[NN * DD];    // x_tilde pong buffer
__device__ float g_h[NN * DD];

// ---------------- f32x2 packed math ----------------------------------------
__device__ __forceinline__ u64 pack2(float s) {
    u64 d;
    asm("mov.b64 %0, {%1, %1};" : "=l"(d) : "f"(s));
    return d;
}
__device__ __forceinline__ void fma2(u64& acc, u64 a, u64 b) {
    asm("fma.rn.f32x2 %0, %1, %2, %0;" : "+l"(acc) : "l"(a), "l"(b));
}
__device__ __forceinline__ float2 unpack2(u64 v) {
    float lo, hi;
    asm("mov.b64 {%0, %1}, %2;" : "=f"(lo), "=f"(hi) : "l"(v));
    return make_float2(lo, hi);
}

// ---------------- init: zero deg/cur + dtype detection ----------------------
__global__ void k_init(const int* __restrict__ ei, const unsigned int* __restrict__ Mw) {
    int i = blockIdx.x * blockDim.x + threadIdx.x;
    if (i < NN) { g_deg[i] = 0; g_cur[i] = 0; }
    if (blockIdx.x == 0) {
        __shared__ int s_or, s_gt;
        if (threadIdx.x == 0) { s_or = 0; s_gt = 0; }
        __syncthreads();
        int t = threadIdx.x;
        if (ei[2 * t + 1] != 0) atomicOr(&s_or, 1);
        if (Mw[t] > 1u)         atomicOr(&s_gt, 1);
        __syncthreads();
        if (threadIdx.x == 0) { g_ei_is64 = (s_or == 0); g_m_is32 = (s_gt == 0); }
    }
}

// ---------------- CSC build -------------------------------------------------
__global__ void k_count(const int* __restrict__ ei) {
    int e = blockIdx.x * blockDim.x + threadIdx.x;
    if (e >= EE) return;
    int c = g_ei_is64 ? ei[2 * (EE + e)] : ei[EE + e];
    atomicAdd(&g_deg[c], 1);
}

__global__ void k_scanA() {
    __shared__ int wsum[32];
    int tid = threadIdx.x, lane = tid & 31, wid = tid >> 5;
    int i = blockIdx.x * 1024 + tid;
    int v = (i < NN) ? g_deg[i] : 0;
    if (i < NN) g_dinv[i] = (v > 0) ? rsqrtf((float)v) : 0.0f;
    int x = v;
#pragma unroll
    for (int o = 1; o < 32; o <<= 1) {
        int t = __shfl_up_sync(0xffffffffu, x, o);
        if (lane >= o) x += t;
    }
    if (lane == 31) wsum[wid] = x;
    __syncthreads();
    if (wid == 0) {
        int s = wsum[lane];
#pragma unroll
        for (int o = 1; o < 32; o <<= 1) {
            int t = __shfl_up_sync(0xffffffffu, s, o);
            if (lane >= o) s += t;
        }
        wsum[lane] = s;
    }
    __syncthreads();
    int woff = (wid > 0) ? wsum[wid - 1] : 0;
    if (i < NN) g_off[i + 1] = woff + x;          // local inclusive
    if (tid == 1023) g_bsum[blockIdx.x] = woff + x;
}

__global__ void k_scanB() {
    __shared__ int s[64];
    int t = threadIdx.x;   // 64 threads
    s[t] = (t < NBLK) ? g_bsum[t] : 0;
    __syncthreads();
#pragma unroll
    for (int o = 1; o < 64; o <<= 1) {
        int v = (t >= o) ? s[t - o] : 0;
        __syncthreads();
        s[t] += v;
        __syncthreads();
    }
    g_bsum[t] = (t > 0) ? s[t - 1] : 0;           // exclusive
}

__global__ void k_scanC() {
    int i = blockIdx.x * 1024 + threadIdx.x;
    int add = g_bsum[blockIdx.x];
    if (i < NN) g_off[i + 1] += add;
    if (i == 0) g_off[0] = 0;
}

__global__ void k_bucket(const int* __restrict__ ei) {
    int e = blockIdx.x * blockDim.x + threadIdx.x;
    if (e >= EE) return;
    int r, c;
    if (g_ei_is64) { r = ei[2 * e]; c = ei[2 * (EE + e)]; }
    else           { r = ei[e];     c = ei[EE + e]; }
    int p = atomicAdd(&g_cur[c], 1);
    g_src[g_off[c] + p] = r;
}

// ---------------- x_tilde init (pre-scaled by dinv[row]) --------------------
__global__ void k_xt0m(const float* __restrict__ x, const void* __restrict__ M) {
    int i = blockIdx.x * blockDim.x + threadIdx.x;   // over (N*D)/4
    if (i >= NN * DD / 4) return;
    uchar4 mv;
    if (g_m_is32) {
        int4 w = ((const int4*)M)[i];
        mv = make_uchar4((unsigned char)w.x, (unsigned char)w.y,
                         (unsigned char)w.z, (unsigned char)w.w);
    } else {
        mv = ((const uchar4*)M)[i];
    }
    ((uchar4*)g_M)[i] = mv;
    float dv = g_dinv[i >> 5];
    float4 xv = ((const float4*)x)[i];
    float4 r;
    r.x = mv.x ? dv * xv.x : 0.0f;
    r.y = mv.y ? dv * xv.y : 0.0f;
    r.z = mv.z ? dv * xv.z : 0.0f;
    r.w = mv.w ? dv * xv.w : 0.0f;
    ((float4*)g_xtA)[i] = r;
}

// ---------------- fused SpMM + GEMM (f32x2), chunked K ----------------------
// xt_in: x_tilde read buffer (never aliases xt_out -> no cross-block hazard).
// Per k-chunk: gather agg column-chunk into sA (FUSE) or load from g_h,
// stage W chunk, packed f32x2 FMA. Fused epilogue writes xt_out / g_h / out.
template <int NOUT, bool FUSE, bool FINAL>
__global__ void __launch_bounds__(256)
k_gemm(const float* __restrict__ xt_in, float* __restrict__ xt_out,
       const float* __restrict__ W, const float* __restrict__ b,
       const float* __restrict__ bias, const float* __restrict__ x,
       float* __restrict__ out, int write_xt) {
    constexpr int NPAIR = NOUT / 32;
    __shared__ float sA[128 * 33];       // [r][kk] chunk
    __shared__ float sW[32 * 130];       // [kk][j] chunk, 8B-aligned pairs
    __shared__ float sB[128];
    int tid = threadIdx.x;
    int wid = tid >> 5, lane = tid & 31;
    int row0 = blockIdx.x * 128;
    int tr = tid >> 4, tc = tid & 15;

    if (tid < NOUT) sB[tid] = FINAL ? b[tid] : (b[tid] + bias[tid]);

    u64 acc[8][NPAIR];
#pragma unroll
    for (int ii = 0; ii < 8; ii++)
#pragma unroll
        for (int jj = 0; jj < NPAIR; jj++) acc[ii][jj] = 0ull;

    const float4* W4 = (const float4*)W;

    for (int kc = 0; kc < 4; kc++) {
        // ---- A chunk ----
        if (FUSE) {
            const float* xbase = xt_in + kc * 32 + lane;
#pragma unroll 1
            for (int t = 0; t < 16; t++) {
                int rloc = wid * 16 + t;
                int node = row0 + rloc;
                float a = 0.f;
                if (node < NN) {
                    int s = g_off[node], e2 = g_off[node + 1];
                    int i = s;
                    for (; i + 4 <= e2; i += 4) {
                        int s0 = g_src[i],   s1 = g_src[i+1];
                        int s2 = g_src[i+2], s3 = g_src[i+3];
                        float v0 = xbase[(size_t)s0 * DD];
                        float v1 = xbase[(size_t)s1 * DD];
                        float v2 = xbase[(size_t)s2 * DD];
                        float v3 = xbase[(size_t)s3 * DD];
                        a += (v0 + v1) + (v2 + v3);
                    }
                    for (; i < e2; i++)
                        a += xbase[(size_t)g_src[i] * DD];
                    a *= g_dinv[node];
                }
                sA[rloc * 33 + lane] = a;
            }
        } else {
            const float4* A4 = (const float4*)g_h;
            for (int t = tid; t < 128 * 8; t += 256) {
                int r = t >> 3, q = t & 7;
                float4 v = (row0 + r < NN) ? A4[(size_t)(row0 + r) * 32 + kc * 8 + q]
                                           : make_float4(0.f, 0.f, 0.f, 0.f);
                float* dst = &sA[r * 33 + q * 4];
                dst[0] = v.x; dst[1] = v.y; dst[2] = v.z; dst[3] = v.w;
            }
        }
        // ---- W chunk ----
        for (int t = tid; t < NOUT * 8; t += 256) {
            int j = t >> 3, q = t & 7;
            float4 v = W4[(size_t)j * 32 + kc * 8 + q];
            int kk = q * 4;
            sW[(kk + 0) * 130 + j] = v.x;
            sW[(kk + 1) * 130 + j] = v.y;
            sW[(kk + 2) * 130 + j] = v.z;
            sW[(kk + 3) * 130 + j] = v.w;
        }
        __syncthreads();
#pragma unroll
        for (int kk = 0; kk < 32; kk++) {
            u64 a2[8], w2[NPAIR];
#pragma unroll
            for (int ii = 0; ii < 8; ii++)
                a2[ii] = pack2(sA[(tr + 16 * ii) * 33 + kk]);
#pragma unroll
            for (int jj = 0; jj < NPAIR; jj++)
                w2[jj] = *(const u64*)&sW[kk * 130 + 2 * tc + 32 * jj];
#pragma unroll
            for (int ii = 0; ii < 8; ii++)
#pragma unroll
                for (int jj = 0; jj < NPAIR; jj++)
                    fma2(acc[ii][jj], a2[ii], w2[jj]);
        }
        __syncthreads();
    }

#pragma unroll
    for (int ii = 0; ii < 8; ii++) {
        int r = row0 + tr + 16 * ii;
        if (r >= NN) continue;
        float dv = (!FINAL) ? g_dinv[r] : 0.f;
#pragma unroll
        for (int jj = 0; jj < NPAIR; jj++) {
            int j0 = 2 * tc + 32 * jj;
            float2 v = unpack2(acc[ii][jj]);
            if (FINAL) {
                v.x += sB[j0];
                v.y += sB[j0 + 1];
                *(float2*)&out[(size_t)r * OUTC + j0] = v;
            } else {
                v.x = fmaxf(v.x + sB[j0], 0.f);
                v.y = fmaxf(v.y + sB[j0 + 1], 0.f);
                size_t idx = (size_t)r * DD + j0;
                if (write_xt) {
                    // next-layer x_tilde, pre-scaled by dinv[r]
                    unsigned char m0 = g_M[idx], m1 = g_M[idx + 1];
                    float2 xv = *(const float2*)&x[idx];
                    float2 tv;
                    tv.x = dv * (m0 ? xv.x : v.x);
                    tv.y = dv * (m1 ? xv.y : v.y);
                    *(float2*)&xt_out[idx] = tv;
                } else {
                    // layer 3: only h is consumed downstream
                    *(float2*)&g_h[idx] = v;
                }
            }
        }
    }
}

// ---------------- launch ----------------------------------------------------
extern "C" void kernel_launch(void* const* d_in, const int* in_sizes, int n_in,
                              void* d_out, int out_size) {
    const int* ei = (const int*)d_in[0];   // [2,E], int32 or int64 (detected)
    const float* x = (const float*)d_in[2];
    const void*  M = d_in[3];              // bool or int32 (detected)
    const float* W1 = (const float*)d_in[4];
    const float* b1 = (const float*)d_in[5];
    const float* c1 = (const float*)d_in[6];
    const float* W2 = (const float*)d_in[7];
    const float* b2 = (const float*)d_in[8];
    const float* c2 = (const float*)d_in[9];
    const float* W3 = (const float*)d_in[10];
    const float* b3 = (const float*)d_in[11];
    const float* c3 = (const float*)d_in[12];
    const float* Wf = (const float*)d_in[13];
    const float* bf = (const float*)d_in[14];
    float* out = (float*)d_out;

    float* xtA; cudaGetSymbolAddress((void**)&xtA, g_xtA);
    float* xtB; cudaGetSymbolAddress((void**)&xtB, g_xtB);

    const int TB = 256;
    int nb_n = (NN + TB - 1) / TB;
    int nb_e = (EE + TB - 1) / TB;
    int nb_xt = (NN * DD / 4 + TB - 1) / TB;
    int nb_gemm = (NN + 127) / 128;

    k_init<<<nb_n, TB>>>(ei, (const unsigned int*)M);
    k_count<<<nb_e, TB>>>(ei);
    k_scanA<<<NBLK, 1024>>>();
    k_scanB<<<1, 64>>>();
    k_scanC<<<NBLK, 1024>>>();
    k_bucket<<<nb_e, TB>>>(ei);
    k_xt0m<<<nb_xt, TB>>>(x, M);

    // ping-pong x_tilde buffers: no kernel reads the buffer it writes
    k_gemm<128, true, false><<<nb_gemm, TB>>>(xtA, xtB, W1, b1, c1, x, nullptr, 1);
    k_gemm<128, true, false><<<nb_gemm, TB>>>(xtB, xtA, W2, b2, c2, x, nullptr, 1);
    k_gemm<128, true, false><<<nb_gemm, TB>>>(xtA, xtB, W3, b3, c3, x, nullptr, 0);
    k_gemm<64, false, true><<<nb_gemm, TB>>>(nullptr, nullptr, Wf, bf, nullptr, nullptr, out, 0);
}

// round 9
// speedup vs baseline: 2.5793x; 2.5793x over previous
#include <cuda_runtime.h>
#include <math.h>
#include <stdint.h>

#define NN 50000
#define EE 800000
#define DD 128
#define OUTC 64
#define NBLK ((NN + 1023) / 1024)   // 49 scan blocks

typedef unsigned long long u64;

// ---------------- scratch (device globals; no allocation allowed) ----------
__device__ int   g_ei_is64;
__device__ int   g_m_is32;
__device__ unsigned char g_M[NN * DD];
__device__ int   g_deg[NN];
__device__ float g_dinv[NN];
__device__ int   g_off[NN + 1];
__device__ int   g_cur[NN];
__device__ int   g_bsum[64];
__device__ int   g_src[EE];
__device__ float g_xt[NN * DD];     // x_tilde, pre-scaled by dinv[row]
__device__ float g_agg[NN * DD];    // aggregated messages
__device__ float g_h[NN * DD];      // layer-3 activations

// ---------------- f32x2 packed math ----------------------------------------
__device__ __forceinline__ u64 pack2(float s) {
    u64 d;
    asm("mov.b64 %0, {%1, %1};" : "=l"(d) : "f"(s));
    return d;
}
__device__ __forceinline__ void fma2(u64& acc, u64 a, u64 b) {
    asm("fma.rn.f32x2 %0, %1, %2, %0;" : "+l"(acc) : "l"(a), "l"(b));
}
__device__ __forceinline__ float2 unpack2(u64 v) {
    float lo, hi;
    asm("mov.b64 {%0, %1}, %2;" : "=f"(lo), "=f"(hi) : "l"(v));
    return make_float2(lo, hi);
}

// ---------------- init: zero deg/cur + dtype detection ----------------------
__global__ void k_init(const int* __restrict__ ei, const unsigned int* __restrict__ Mw) {
    int i = blockIdx.x * blockDim.x + threadIdx.x;
    if (i < NN) { g_deg[i] = 0; g_cur[i] = 0; }
    if (blockIdx.x == 0) {
        __shared__ int s_or, s_gt;
        if (threadIdx.x == 0) { s_or = 0; s_gt = 0; }
        __syncthreads();
        int t = threadIdx.x;
        if (ei[2 * t + 1] != 0) atomicOr(&s_or, 1);
        if (Mw[t] > 1u)         atomicOr(&s_gt, 1);
        __syncthreads();
        if (threadIdx.x == 0) { g_ei_is64 = (s_or == 0); g_m_is32 = (s_gt == 0); }
    }
}

// ---------------- CSC build -------------------------------------------------
__global__ void k_count(const int* __restrict__ ei) {
    int e = blockIdx.x * blockDim.x + threadIdx.x;
    if (e >= EE) return;
    int c = g_ei_is64 ? ei[2 * (EE + e)] : ei[EE + e];
    atomicAdd(&g_deg[c], 1);
}

__global__ void k_scanA() {
    __shared__ int wsum[32];
    int tid = threadIdx.x, lane = tid & 31, wid = tid >> 5;
    int i = blockIdx.x * 1024 + tid;
    int v = (i < NN) ? g_deg[i] : 0;
    if (i < NN) g_dinv[i] = (v > 0) ? rsqrtf((float)v) : 0.0f;
    int x = v;
#pragma unroll
    for (int o = 1; o < 32; o <<= 1) {
        int t = __shfl_up_sync(0xffffffffu, x, o);
        if (lane >= o) x += t;
    }
    if (lane == 31) wsum[wid] = x;
    __syncthreads();
    if (wid == 0) {
        int s = wsum[lane];
#pragma unroll
        for (int o = 1; o < 32; o <<= 1) {
            int t = __shfl_up_sync(0xffffffffu, s, o);
            if (lane >= o) s += t;
        }
        wsum[lane] = s;
    }
    __syncthreads();
    int woff = (wid > 0) ? wsum[wid - 1] : 0;
    if (i < NN) g_off[i + 1] = woff + x;          // local inclusive
    if (tid == 1023) g_bsum[blockIdx.x] = woff + x;
}

__global__ void k_scanB() {
    __shared__ int s[64];
    int t = threadIdx.x;   // 64 threads
    s[t] = (t < NBLK) ? g_bsum[t] : 0;
    __syncthreads();
#pragma unroll
    for (int o = 1; o < 64; o <<= 1) {
        int v = (t >= o) ? s[t - o] : 0;
        __syncthreads();
        s[t] += v;
        __syncthreads();
    }
    g_bsum[t] = (t > 0) ? s[t - 1] : 0;           // exclusive
}

__global__ void k_scanC() {
    int i = blockIdx.x * 1024 + threadIdx.x;
    int add = g_bsum[blockIdx.x];
    if (i < NN) g_off[i + 1] += add;
    if (i == 0) g_off[0] = 0;
}

__global__ void k_bucket(const int* __restrict__ ei) {
    int e = blockIdx.x * blockDim.x + threadIdx.x;
    if (e >= EE) return;
    int r, c;
    if (g_ei_is64) { r = ei[2 * e]; c = ei[2 * (EE + e)]; }
    else           { r = ei[e];     c = ei[EE + e]; }
    int p = atomicAdd(&g_cur[c], 1);
    g_src[g_off[c] + p] = r;
}

// ---------------- x_tilde init (pre-scaled by dinv[row]) --------------------
__global__ void k_xt0m(const float* __restrict__ x, const void* __restrict__ M) {
    int i = blockIdx.x * blockDim.x + threadIdx.x;   // over (N*D)/4
    if (i >= NN * DD / 4) return;
    uchar4 mv;
    if (g_m_is32) {
        int4 w = ((const int4*)M)[i];
        mv = make_uchar4((unsigned char)w.x, (unsigned char)w.y,
                         (unsigned char)w.z, (unsigned char)w.w);
    } else {
        mv = ((const uchar4*)M)[i];
    }
    ((uchar4*)g_M)[i] = mv;
    float dv = g_dinv[i >> 5];
    float4 xv = ((const float4*)x)[i];
    float4 r;
    r.x = mv.x ? dv * xv.x : 0.0f;
    r.y = mv.y ? dv * xv.y : 0.0f;
    r.z = mv.z ? dv * xv.z : 0.0f;
    r.w = mv.w ? dv * xv.w : 0.0f;
    ((float4*)g_xt)[i] = r;
}

// ---------------- SpMM: one warp per destination node -----------------------
// agg[c] = dinv[c] * sum_{src in col c} xt_scaled[src]   (no per-edge weight)
__global__ void k_spmm() {
    int warp = (blockIdx.x * blockDim.x + threadIdx.x) >> 5;
    if (warp >= NN) return;
    int lane = threadIdx.x & 31;
    int s = g_off[warp], t = g_off[warp + 1];
    const float4* xt4 = (const float4*)g_xt;
    float4 acc = make_float4(0.f, 0.f, 0.f, 0.f);
    int i = s;
    for (; i + 4 <= t; i += 4) {
        int s0 = g_src[i],   s1 = g_src[i+1];
        int s2 = g_src[i+2], s3 = g_src[i+3];
        float4 v0 = xt4[s0 * 32 + lane];
        float4 v1 = xt4[s1 * 32 + lane];
        float4 v2 = xt4[s2 * 32 + lane];
        float4 v3 = xt4[s3 * 32 + lane];
        acc.x += (v0.x + v1.x) + (v2.x + v3.x);
        acc.y += (v0.y + v1.y) + (v2.y + v3.y);
        acc.z += (v0.z + v1.z) + (v2.z + v3.z);
        acc.w += (v0.w + v1.w) + (v2.w + v3.w);
    }
    for (; i < t; i++) {
        float4 v = xt4[g_src[i] * 32 + lane];
        acc.x += v.x; acc.y += v.y; acc.z += v.z; acc.w += v.w;
    }
    float dv = g_dinv[warp];
    acc.x *= dv; acc.y *= dv; acc.z *= dv; acc.w *= dv;
    ((float4*)g_agg)[warp * 32 + lane] = acc;
}

// ---------------- GEMM with packed f32x2 FMA ---------------------------------
// D[128 x NOUT] = A[128 x 128] @ W[NOUT x 128]^T, A = g_agg (g_h for FINAL).
// Epilogue: hidden layers write ONLY next x_tilde (pre-scaled) or, for layer 3,
// ONLY g_h. Final writes out.
template <int NOUT, bool FINAL>
__global__ void __launch_bounds__(256)
k_gemm(const float* __restrict__ W, const float* __restrict__ b,
       const float* __restrict__ bias, const float* __restrict__ x,
       float* __restrict__ out, int write_xt) {
    constexpr int NPAIR = NOUT / 32;
    __shared__ float sA[128 * 33];       // [r][kk] chunk
    __shared__ float sW[32 * 130];       // [kk][j] chunk, 8B-aligned pairs
    __shared__ float sB[128];
    int tid = threadIdx.x;
    int row0 = blockIdx.x * 128;
    int tr = tid >> 4, tc = tid & 15;

    if (tid < NOUT) sB[tid] = FINAL ? b[tid] : (b[tid] + bias[tid]);

    u64 acc[8][NPAIR];
#pragma unroll
    for (int ii = 0; ii < 8; ii++)
#pragma unroll
        for (int jj = 0; jj < NPAIR; jj++) acc[ii][jj] = 0ull;

    const float4* A4 = (const float4*)(FINAL ? g_h : g_agg);
    const float4* W4 = (const float4*)W;

    for (int kc = 0; kc < 4; kc++) {
        for (int t = tid; t < 128 * 8; t += 256) {
            int r = t >> 3, q = t & 7;
            float4 v = (row0 + r < NN) ? A4[(size_t)(row0 + r) * 32 + kc * 8 + q]
                                       : make_float4(0.f, 0.f, 0.f, 0.f);
            float* dst = &sA[r * 33 + q * 4];
            dst[0] = v.x; dst[1] = v.y; dst[2] = v.z; dst[3] = v.w;
        }
        for (int t = tid; t < NOUT * 8; t += 256) {
            int j = t >> 3, q = t & 7;
            float4 v = W4[(size_t)j * 32 + kc * 8 + q];
            int kk = q * 4;
            sW[(kk + 0) * 130 + j] = v.x;
            sW[(kk + 1) * 130 + j] = v.y;
            sW[(kk + 2) * 130 + j] = v.z;
            sW[(kk + 3) * 130 + j] = v.w;
        }
        __syncthreads();
#pragma unroll
        for (int kk = 0; kk < 32; kk++) {
            u64 a2[8], w2[NPAIR];
#pragma unroll
            for (int ii = 0; ii < 8; ii++)
                a2[ii] = pack2(sA[(tr + 16 * ii) * 33 + kk]);
#pragma unroll
            for (int jj = 0; jj < NPAIR; jj++)
                w2[jj] = *(const u64*)&sW[kk * 130 + 2 * tc + 32 * jj];
#pragma unroll
            for (int ii = 0; ii < 8; ii++)
#pragma unroll
                for (int jj = 0; jj < NPAIR; jj++)
                    fma2(acc[ii][jj], a2[ii], w2[jj]);
        }
        __syncthreads();
    }

#pragma unroll
    for (int ii = 0; ii < 8; ii++) {
        int r = row0 + tr + 16 * ii;
        if (r >= NN) continue;
        float dv = (!FINAL) ? g_dinv[r] : 0.f;
#pragma unroll
        for (int jj = 0; jj < NPAIR; jj++) {
            int j0 = 2 * tc + 32 * jj;
            float2 v = unpack2(acc[ii][jj]);
            if (FINAL) {
                v.x += sB[j0];
                v.y += sB[j0 + 1];
                *(float2*)&out[(size_t)r * OUTC + j0] = v;
            } else {
                v.x = fmaxf(v.x + sB[j0], 0.f);
                v.y = fmaxf(v.y + sB[j0 + 1], 0.f);
                size_t idx = (size_t)r * DD + j0;
                if (write_xt) {
                    // layers 1-2: only next x_tilde is consumed (pre-scaled)
                    unsigned char m0 = g_M[idx], m1 = g_M[idx + 1];
                    float2 xv = *(const float2*)&x[idx];
                    float2 tv;
                    tv.x = dv * (m0 ? xv.x : v.x);
                    tv.y = dv * (m1 ? xv.y : v.y);
                    *(float2*)&g_xt[idx] = tv;
                } else {
                    // layer 3: only h is consumed
                    *(float2*)&g_h[idx] = v;
                }
            }
        }
    }
}

// ---------------- launch ----------------------------------------------------
extern "C" void kernel_launch(void* const* d_in, const int* in_sizes, int n_in,
                              void* d_out, int out_size) {
    const int* ei = (const int*)d_in[0];   // [2,E], int32 or int64 (detected)
    const float* x = (const float*)d_in[2];
    const void*  M = d_in[3];              // bool or int32 (detected)
    const float* W1 = (const float*)d_in[4];
    const float* b1 = (const float*)d_in[5];
    const float* c1 = (const float*)d_in[6];
    const float* W2 = (const float*)d_in[7];
    const float* b2 = (const float*)d_in[8];
    const float* c2 = (const float*)d_in[9];
    const float* W3 = (const float*)d_in[10];
    const float* b3 = (const float*)d_in[11];
    const float* c3 = (const float*)d_in[12];
    const float* Wf = (const float*)d_in[13];
    const float* bf = (const float*)d_in[14];
    float* out = (float*)d_out;

    const int TB = 256;
    int nb_n = (NN + TB - 1) / TB;
    int nb_e = (EE + TB - 1) / TB;
    int nb_xt = (NN * DD / 4 + TB - 1) / TB;
    int nb_spmm = (NN * 32 + TB - 1) / TB;   // 1 warp per node
    int nb_gemm = (NN + 127) / 128;

    k_init<<<nb_n, TB>>>(ei, (const unsigned int*)M);
    k_count<<<nb_e, TB>>>(ei);
    k_scanA<<<NBLK, 1024>>>();
    k_scanB<<<1, 64>>>();
    k_scanC<<<NBLK, 1024>>>();
    k_bucket<<<nb_e, TB>>>(ei);
    k_xt0m<<<nb_xt, TB>>>(x, M);

    k_spmm<<<nb_spmm, TB>>>();
    k_gemm<128, false><<<nb_gemm, TB>>>(W1, b1, c1, x, nullptr, 1);
    k_spmm<<<nb_spmm, TB>>>();
    k_gemm<128, false><<<nb_gemm, TB>>>(W2, b2, c2, x, nullptr, 1);
    k_spmm<<<nb_spmm, TB>>>();
    k_gemm<128, false><<<nb_gemm, TB>>>(W3, b3, c3, x, nullptr, 0);
    k_gemm<64, true><<<nb_gemm, TB>>>(Wf, bf, nullptr, nullptr, out, 0);
}

// round 10
// speedup vs baseline: 2.8618x; 1.1095x over previous
#include <cuda_runtime.h>
#include <cuda_fp16.h>
#include <math.h>
#include <stdint.h>

#define NN 50000
#define EE 800000
#define DD 128
#define OUTC 64
#define NBLK ((NN + 1023) / 1024)   // 49 scan blocks

typedef unsigned long long u64;

// ---------------- scratch (device globals; no allocation allowed) ----------
__device__ int   g_ei_is64;
__device__ int   g_m_is32;
__device__ unsigned char g_M[NN * DD];
__device__ int   g_deg[NN];
__device__ float g_dinv[NN];
__device__ int   g_off[NN + 1];
__device__ int   g_cur[NN];
__device__ int   g_bsum[64];
__device__ int   g_src[EE];
__device__ __half g_xt[NN * DD];    // x_tilde, fp16, pre-scaled by dinv[row]
__device__ float g_agg[NN * DD];    // aggregated messages (fp32)
__device__ float g_h[NN * DD];      // layer-3 activations

// ---------------- f32x2 packed math ----------------------------------------
__device__ __forceinline__ u64 pack2(float s) {
    u64 d;
    asm("mov.b64 %0, {%1, %1};" : "=l"(d) : "f"(s));
    return d;
}
__device__ __forceinline__ void fma2(u64& acc, u64 a, u64 b) {
    asm("fma.rn.f32x2 %0, %1, %2, %0;" : "+l"(acc) : "l"(a), "l"(b));
}
__device__ __forceinline__ float2 unpack2(u64 v) {
    float lo, hi;
    asm("mov.b64 {%0, %1}, %2;" : "=f"(lo), "=f"(hi) : "l"(v));
    return make_float2(lo, hi);
}

// ---------------- init: zero deg/cur + dtype detection ----------------------
__global__ void k_init(const int* __restrict__ ei, const unsigned int* __restrict__ Mw) {
    int i = blockIdx.x * blockDim.x + threadIdx.x;
    if (i < NN) { g_deg[i] = 0; g_cur[i] = 0; }
    if (blockIdx.x == 0) {
        __shared__ int s_or, s_gt;
        if (threadIdx.x == 0) { s_or = 0; s_gt = 0; }
        __syncthreads();
        int t = threadIdx.x;
        if (ei[2 * t + 1] != 0) atomicOr(&s_or, 1);
        if (Mw[t] > 1u)         atomicOr(&s_gt, 1);
        __syncthreads();
        if (threadIdx.x == 0) { g_ei_is64 = (s_or == 0); g_m_is32 = (s_gt == 0); }
    }
}

// ---------------- CSC build -------------------------------------------------
__global__ void k_count(const int* __restrict__ ei) {
    int e = blockIdx.x * blockDim.x + threadIdx.x;
    if (e >= EE) return;
    int c = g_ei_is64 ? ei[2 * (EE + e)] : ei[EE + e];
    atomicAdd(&g_deg[c], 1);
}

__global__ void k_scanA() {
    __shared__ int wsum[32];
    int tid = threadIdx.x, lane = tid & 31, wid = tid >> 5;
    int i = blockIdx.x * 1024 + tid;
    int v = (i < NN) ? g_deg[i] : 0;
    if (i < NN) g_dinv[i] = (v > 0) ? rsqrtf((float)v) : 0.0f;
    int x = v;
#pragma unroll
    for (int o = 1; o < 32; o <<= 1) {
        int t = __shfl_up_sync(0xffffffffu, x, o);
        if (lane >= o) x += t;
    }
    if (lane == 31) wsum[wid] = x;
    __syncthreads();
    if (wid == 0) {
        int s = wsum[lane];
#pragma unroll
        for (int o = 1; o < 32; o <<= 1) {
            int t = __shfl_up_sync(0xffffffffu, s, o);
            if (lane >= o) s += t;
        }
        wsum[lane] = s;
    }
    __syncthreads();
    int woff = (wid > 0) ? wsum[wid - 1] : 0;
    if (i < NN) g_off[i + 1] = woff + x;          // local inclusive
    if (tid == 1023) g_bsum[blockIdx.x] = woff + x;
}

__global__ void k_scanB() {
    __shared__ int s[64];
    int t = threadIdx.x;   // 64 threads
    s[t] = (t < NBLK) ? g_bsum[t] : 0;
    __syncthreads();
#pragma unroll
    for (int o = 1; o < 64; o <<= 1) {
        int v = (t >= o) ? s[t - o] : 0;
        __syncthreads();
        s[t] += v;
        __syncthreads();
    }
    g_bsum[t] = (t > 0) ? s[t - 1] : 0;           // exclusive
}

__global__ void k_scanC() {
    int i = blockIdx.x * 1024 + threadIdx.x;
    int add = g_bsum[blockIdx.x];
    if (i < NN) g_off[i + 1] += add;
    if (i == 0) g_off[0] = 0;
}

__global__ void k_bucket(const int* __restrict__ ei) {
    int e = blockIdx.x * blockDim.x + threadIdx.x;
    if (e >= EE) return;
    int r, c;
    if (g_ei_is64) { r = ei[2 * e]; c = ei[2 * (EE + e)]; }
    else           { r = ei[e];     c = ei[EE + e]; }
    int p = atomicAdd(&g_cur[c], 1);
    g_src[g_off[c] + p] = r;
}

// ---------------- x_tilde init (fp16, pre-scaled by dinv[row]) --------------
__global__ void k_xt0m(const float* __restrict__ x, const void* __restrict__ M) {
    int i = blockIdx.x * blockDim.x + threadIdx.x;   // over (N*D)/4
    if (i >= NN * DD / 4) return;
    uchar4 mv;
    if (g_m_is32) {
        int4 w = ((const int4*)M)[i];
        mv = make_uchar4((unsigned char)w.x, (unsigned char)w.y,
                         (unsigned char)w.z, (unsigned char)w.w);
    } else {
        mv = ((const uchar4*)M)[i];
    }
    ((uchar4*)g_M)[i] = mv;
    float dv = g_dinv[i >> 5];
    float4 xv = ((const float4*)x)[i];
    __half2 h01 = __floats2half2_rn(mv.x ? dv * xv.x : 0.0f,
                                    mv.y ? dv * xv.y : 0.0f);
    __half2 h23 = __floats2half2_rn(mv.z ? dv * xv.z : 0.0f,
                                    mv.w ? dv * xv.w : 0.0f);
    uint2 packed;
    packed.x = *(unsigned int*)&h01;
    packed.y = *(unsigned int*)&h23;
    ((uint2*)g_xt)[i] = packed;
}

// ---------------- SpMM: one warp per destination node (fp16 gather) ---------
// agg[c] = dinv[c] * sum_{src in col c} xt_scaled[src]; accumulate in fp32.
__global__ void k_spmm() {
    int warp = (blockIdx.x * blockDim.x + threadIdx.x) >> 5;
    if (warp >= NN) return;
    int lane = threadIdx.x & 31;
    int s = g_off[warp], t = g_off[warp + 1];
    const uint2* xt2 = (const uint2*)g_xt;   // 8B = 4 halfs per lane
    float4 acc = make_float4(0.f, 0.f, 0.f, 0.f);
    int i = s;
    for (; i + 4 <= t; i += 4) {
        int s0 = g_src[i],   s1 = g_src[i+1];
        int s2 = g_src[i+2], s3 = g_src[i+3];
        uint2 r0 = xt2[s0 * 32 + lane];
        uint2 r1 = xt2[s1 * 32 + lane];
        uint2 r2 = xt2[s2 * 32 + lane];
        uint2 r3 = xt2[s3 * 32 + lane];
#pragma unroll
        for (int u = 0; u < 4; u++) {
            uint2 rv = (u == 0) ? r0 : (u == 1) ? r1 : (u == 2) ? r2 : r3;
            float2 f01 = __half22float2(*(__half2*)&rv.x);
            float2 f23 = __half22float2(*(__half2*)&rv.y);
            acc.x += f01.x; acc.y += f01.y; acc.z += f23.x; acc.w += f23.y;
        }
    }
    for (; i < t; i++) {
        uint2 rv = xt2[g_src[i] * 32 + lane];
        float2 f01 = __half22float2(*(__half2*)&rv.x);
        float2 f23 = __half22float2(*(__half2*)&rv.y);
        acc.x += f01.x; acc.y += f01.y; acc.z += f23.x; acc.w += f23.y;
    }
    float dv = g_dinv[warp];
    acc.x *= dv; acc.y *= dv; acc.z *= dv; acc.w *= dv;
    ((float4*)g_agg)[warp * 32 + lane] = acc;
}

// ---------------- GEMM with packed f32x2 FMA ---------------------------------
// D[128 x NOUT] = A[128 x 128] @ W[NOUT x 128]^T, A = g_agg (g_h for FINAL).
// Hidden layers: write ONLY next x_tilde (fp16, pre-scaled) or, layer 3, g_h.
template <int NOUT, bool FINAL>
__global__ void __launch_bounds__(256)
k_gemm(const float* __restrict__ W, const float* __restrict__ b,
       const float* __restrict__ bias, const float* __restrict__ x,
       float* __restrict__ out, int write_xt) {
    constexpr int NPAIR = NOUT / 32;
    __shared__ float sA[128 * 33];       // [r][kk] chunk
    __shared__ float sW[32 * 130];       // [kk][j] chunk, 8B-aligned pairs
    __shared__ float sB[128];
    int tid = threadIdx.x;
    int row0 = blockIdx.x * 128;
    int tr = tid >> 4, tc = tid & 15;

    if (tid < NOUT) sB[tid] = FINAL ? b[tid] : (b[tid] + bias[tid]);

    u64 acc[8][NPAIR];
#pragma unroll
    for (int ii = 0; ii < 8; ii++)
#pragma unroll
        for (int jj = 0; jj < NPAIR; jj++) acc[ii][jj] = 0ull;

    const float4* A4 = (const float4*)(FINAL ? g_h : g_agg);
    const float4* W4 = (const float4*)W;

    for (int kc = 0; kc < 4; kc++) {
        for (int t = tid; t < 128 * 8; t += 256) {
            int r = t >> 3, q = t & 7;
            float4 v = (row0 + r < NN) ? A4[(size_t)(row0 + r) * 32 + kc * 8 + q]
                                       : make_float4(0.f, 0.f, 0.f, 0.f);
            float* dst = &sA[r * 33 + q * 4];
            dst[0] = v.x; dst[1] = v.y; dst[2] = v.z; dst[3] = v.w;
        }
        for (int t = tid; t < NOUT * 8; t += 256) {
            int j = t >> 3, q = t & 7;
            float4 v = W4[(size_t)j * 32 + kc * 8 + q];
            int kk = q * 4;
            sW[(kk + 0) * 130 + j] = v.x;
            sW[(kk + 1) * 130 + j] = v.y;
            sW[(kk + 2) * 130 + j] = v.z;
            sW[(kk + 3) * 130 + j] = v.w;
        }
        __syncthreads();
#pragma unroll
        for (int kk = 0; kk < 32; kk++) {
            u64 a2[8], w2[NPAIR];
#pragma unroll
            for (int ii = 0; ii < 8; ii++)
                a2[ii] = pack2(sA[(tr + 16 * ii) * 33 + kk]);
#pragma unroll
            for (int jj = 0; jj < NPAIR; jj++)
                w2[jj] = *(const u64*)&sW[kk * 130 + 2 * tc + 32 * jj];
#pragma unroll
            for (int ii = 0; ii < 8; ii++)
#pragma unroll
                for (int jj = 0; jj < NPAIR; jj++)
                    fma2(acc[ii][jj], a2[ii], w2[jj]);
        }
        __syncthreads();
    }

#pragma unroll
    for (int ii = 0; ii < 8; ii++) {
        int r = row0 + tr + 16 * ii;
        if (r >= NN) continue;
        float dv = (!FINAL) ? g_dinv[r] : 0.f;
#pragma unroll
        for (int jj = 0; jj < NPAIR; jj++) {
            int j0 = 2 * tc + 32 * jj;
            float2 v = unpack2(acc[ii][jj]);
            if (FINAL) {
                v.x += sB[j0];
                v.y += sB[j0 + 1];
                *(float2*)&out[(size_t)r * OUTC + j0] = v;
            } else {
                v.x = fmaxf(v.x + sB[j0], 0.f);
                v.y = fmaxf(v.y + sB[j0 + 1], 0.f);
                size_t idx = (size_t)r * DD + j0;
                if (write_xt) {
                    // layers 1-2: only next x_tilde is consumed (fp16, pre-scaled)
                    unsigned char m0 = g_M[idx], m1 = g_M[idx + 1];
                    float2 xv = *(const float2*)&x[idx];
                    __half2 tv = __floats2half2_rn(dv * (m0 ? xv.x : v.x),
                                                   dv * (m1 ? xv.y : v.y));
                    *(__half2*)&g_xt[idx] = tv;
                } else {
                    // layer 3: only h is consumed
                    *(float2*)&g_h[idx] = v;
                }
            }
        }
    }
}

// ---------------- launch ----------------------------------------------------
extern "C" void kernel_launch(void* const* d_in, const int* in_sizes, int n_in,
                              void* d_out, int out_size) {
    const int* ei = (const int*)d_in[0];   // [2,E], int32 or int64 (detected)
    const float* x = (const float*)d_in[2];
    const void*  M = d_in[3];              // bool or int32 (detected)
    const float* W1 = (const float*)d_in[4];
    const float* b1 = (const float*)d_in[5];
    const float* c1 = (const float*)d_in[6];
    const float* W2 = (const float*)d_in[7];
    const float* b2 = (const float*)d_in[8];
    const float* c2 = (const float*)d_in[9];
    const float* W3 = (const float*)d_in[10];
    const float* b3 = (const float*)d_in[11];
    const float* c3 = (const float*)d_in[12];
    const float* Wf = (const float*)d_in[13];
    const float* bf = (const float*)d_in[14];
    float* out = (float*)d_out;

    const int TB = 256;
    int nb_n = (NN + TB - 1) / TB;
    int nb_e = (EE + TB - 1) / TB;
    int nb_xt = (NN * DD / 4 + TB - 1) / TB;
    int nb_spmm = (NN * 32 + TB - 1) / TB;   // 1 warp per node
    int nb_gemm = (NN + 127) / 128;

    k_init<<<nb_n, TB>>>(ei, (const unsigned int*)M);
    k_count<<<nb_e, TB>>>(ei);
    k_scanA<<<NBLK, 1024>>>();
    k_scanB<<<1, 64>>>();
    k_scanC<<<NBLK, 1024>>>();
    k_bucket<<<nb_e, TB>>>(ei);
    k_xt0m<<<nb_xt, TB>>>(x, M);

    k_spmm<<<nb_spmm, TB>>>();
    k_gemm<128, false><<<nb_gemm, TB>>>(W1, b1, c1, x, nullptr, 1);
    k_spmm<<<nb_spmm, TB>>>();
    k_gemm<128, false><<<nb_gemm, TB>>>(W2, b2, c2, x, nullptr, 1);
    k_spmm<<<nb_spmm, TB>>>();
    k_gemm<128, false><<<nb_gemm, TB>>>(W3, b3, c3, x, nullptr, 0);
    k_gemm<64, true><<<nb_gemm, TB>>>(Wf, bf, nullptr, nullptr, out, 0);
}